// round 12
// baseline (speedup 1.0000x reference)
#include <cuda_runtime.h>
#include <cuda_bf16.h>

#define BATCH 16
#define N 256
#define DIM 128

// Scratch (device globals: allocation-free per harness rules)
__device__ float          g_dist[BATCH * N * N];   // 4 MB fp32 distances
__device__ unsigned short g_cost[BATCH * N * N];   // 2 MB u16: (quantized c)<<1
__device__ double         g_bsum[BATCH];           // per-batch matched sums

#define QSCALE 128.0f
#define QMAX   4095    // stored value c' = c<<1 <= 8190; d' = S'+rc' < 2^14

// ---------------------------------------------------------------------------
// Kernel A: pairwise L2 distances + quantization (stored pre-shifted <<1).
// ---------------------------------------------------------------------------
__global__ __launch_bounds__(256) void dist_kernel(const float* __restrict__ pred,
                                                   const float* __restrict__ tgt) {
    __shared__ float sp[16 * 132];
    __shared__ float st[16 * 132];
    const int b  = blockIdx.z;
    const int rt = blockIdx.y;
    const int ct = blockIdx.x;
    const int tid = threadIdx.x;

    const float4* p4 = (const float4*)(pred + (size_t)(b * N + rt * 16) * DIM);
    const float4* t4 = (const float4*)(tgt  + (size_t)(b * N + ct * 16) * DIM);
    for (int idx = tid; idx < 512; idx += 256) {
        int r = idx >> 5, c = idx & 31;
        *(float4*)&sp[r * 132 + c * 4] = p4[idx];
        *(float4*)&st[r * 132 + c * 4] = t4[idx];
    }
    __syncthreads();

    const int ti = tid >> 4;
    const int tj = tid & 15;
    float acc = 0.f;
#pragma unroll
    for (int d4 = 0; d4 < 32; ++d4) {
        float4 a = *(const float4*)&sp[ti * 132 + d4 * 4];
        float4 c = *(const float4*)&st[tj * 132 + d4 * 4];
        float dx = a.x - c.x, dy = a.y - c.y, dz = a.z - c.z, dw = a.w - c.w;
        acc += dx * dx + dy * dy + dz * dz + dw * dw;
    }
    float dd = sqrtf(acc);
    size_t o = ((size_t)b << 16) + (size_t)(rt * 16 + ti) * N + (ct * 16 + tj);
    g_dist[o] = dd;
    int q = __float2int_rn(dd * QSCALE);
    q = q > QMAX ? QMAX : q;
    g_cost[o] = (unsigned short)(q << 1);   // pre-shifted for cheap (c<<17) extract
}

// ---------------------------------------------------------------------------
// Kernel B: per-batch Jonker-Volgenant LSA on pre-shifted u16 costs in shared.
//   Warp-0 Dijkstra, (d<<17 | p<<8 | j) packed redux-min.
//   Critical path: LDS row -> pre -> cand -> candTree -> min(treeOld) -> REDUX.
//   Dp/way relax, freeze, and treeOld recompute run in the next-LDS shadow.
//   Terminal step ALSO applies the cand relax (way correctness). Frozen
//   columns: vpk += 2^31 (wrap-free cands never win / never beat frozen Dp),
//   Dp |= 2^31 (tree exclusion). Duals decoded from frozen Dp at search end.
//   Step body 2x-unrolled via macro + goto to halve backedge cost.
// ---------------------------------------------------------------------------
// dynamic smem layout (bytes)
#define OFF_COST 0                       // u16[65536] = 131072
#define OFF_U    131072                  // u32[257]   = 1028  -> 132100
#define OFF_P    132100                  // u16[257]   = 514   -> 132614
#define OFF_WAY  132624                  // u16[256]   = 512   -> 133136 (16-aligned)
#define OFF_RMIN 133136                  // u16[256]   = 512   -> 133648 (16-aligned)
#define OFF_ROWT 133648                  // u32[8]     = 32    -> 133680
#define OFF_SRED 133680                  // double[8]  = 64    -> 133744
#define SMEM_B   133744

#define JROOT 0x1FF                      // way-chain root marker

extern __shared__ char s_raw[];

__global__ __launch_bounds__(256) void hungarian_kernel() {
    const int b   = blockIdx.x;
    const int tid = threadIdx.x;

    unsigned short* cost  = (unsigned short*)(s_raw + OFF_COST);
    unsigned*       u_    = (unsigned*)(s_raw + OFF_U);         // u<<17, 1-based
    unsigned short* p_    = (unsigned short*)(s_raw + OFF_P);   // p_[j+1], 0 = free
    unsigned short* way0_ = (unsigned short*)(s_raw + OFF_WAY); // 0-based cols
    unsigned short* srmin = (unsigned short*)(s_raw + OFF_RMIN);
    unsigned*       srowt = (unsigned*)(s_raw + OFF_ROWT);
    double*         sred  = (double*)(s_raw + OFF_SRED);

    // ---- Phase 1: copy quantized costs into shared, init state ----
    const uint4* csrc = (const uint4*)(g_cost + ((size_t)b << 16));
    uint4* cdst = (uint4*)cost;
    for (int idx = tid; idx < (N * N) / 8; idx += 256) cdst[idx] = csrc[idx];
    for (int i = tid; i < N + 1; i += 256) { u_[i] = 0u; p_[i] = 0; }
    __syncthreads();

    // ---- Phase 2: warp 0 runs the LSA ----
    if (tid < 32) {
        const unsigned FULL = 0xffffffffu;
        const int lane = tid;

        // Column reduction in the stored (c<<1) domain.
        unsigned vmin[8]; int rmin[8];
#pragma unroll
        for (int k = 0; k < 8; ++k) { vmin[k] = 0xFFFFFFFFu; rmin[k] = 0; }
        for (int r = 0; r < N; ++r) {
            uint4 cc = ((const uint4*)(cost + (r << 8)))[lane];
            unsigned wv[4] = {cc.x, cc.y, cc.z, cc.w};
#pragma unroll
            for (int k = 0; k < 8; ++k) {
                unsigned c = (wv[k >> 1] >> ((k & 1) * 16)) & 0xFFFFu;
                if (c < vmin[k]) { vmin[k] = c; rmin[k] = r; }
            }
        }
        {
            unsigned a0 = (unsigned)rmin[0] | ((unsigned)rmin[1] << 16);
            unsigned a1 = (unsigned)rmin[2] | ((unsigned)rmin[3] << 16);
            unsigned a2 = (unsigned)rmin[4] | ((unsigned)rmin[5] << 16);
            unsigned a3 = (unsigned)rmin[6] | ((unsigned)rmin[7] << 16);
            ((uint4*)srmin)[lane] = make_uint4(a0, a1, a2, a3);
        }
        if (lane < 8) srowt[lane] = 0u;
        __syncwarp();
        // Greedy pre-assignment: column j -> rmin[j] if that row is still free.
        if (lane == 0) {
            for (int j = 0; j < N; ++j) {
                int r = srmin[j];
                unsigned wd = srowt[r >> 5];
                if (!((wd >> (r & 31)) & 1u)) {
                    srowt[r >> 5] = wd | (1u << (r & 31));
                    p_[j + 1] = (unsigned short)(r + 1);
                }
            }
        }
        __syncwarp();

        unsigned vsh[8];                   // v<<17 == (stored c')<<16
#pragma unroll
        for (int k = 0; k < 8; ++k) vsh[k] = vmin[k] << 16;
        unsigned rt[8];
#pragma unroll
        for (int w = 0; w < 8; ++w) rt[w] = srowt[w];

        // base pointer for this lane's 16-byte row slice (offset by t_i*2-512)
        const char* cbase = (const char*)cost - 512 + lane * 16;

        // ---- Dijkstra for each unassigned row ----
        for (int w = 0; w < 8; ++w) {
            unsigned freeb = ~rt[w];
            while (freeb) {
                const int bz = __ffs(freeb) - 1;
                freeb &= freeb - 1;
                const int i = w * 32 + bz + 1;     // 1-based start row; u_[i]==0

                unsigned vpk[8], Dp[8];
                int way[8];
#pragma unroll
                for (int k = 0; k < 8; ++k) {
                    int j = (lane << 3) + k;
                    vpk[k] = (((unsigned)p_[j + 1] << 8) | (unsigned)j) - vsh[k];
                    Dp[k] = 0xFFFFFFFFu;
                    way[k] = JROOT;
                }

                unsigned t_i = (unsigned)i << 8;   // = i0 * 256
                unsigned smask = 0u, u0sh = 0u, mush, treeOld = 0xFFFFFFFFu;
                int j0 = JROOT, jfinal;

// One Dijkstra step. Critical path: LDS -> pre -> cand -> candTree ->
// min(treeOld) -> REDUX -> decode -> next LDS. Shadow: relax, freeze, treeOld.
#define DIJK_STEP                                                             \
                {                                                             \
                    const uint4 cc = *(const uint4*)(cbase + t_i * 2);        \
                    const unsigned bsh = smask - u0sh;                        \
                    const unsigned w0 = cc.x, w1 = cc.y, w2 = cc.z, w3 = cc.w;\
                    unsigned pre[8];                                          \
                    pre[0] = w0 << 16; pre[1] = w0 & 0xFFFF0000u;             \
                    pre[2] = w1 << 16; pre[3] = w1 & 0xFFFF0000u;             \
                    pre[4] = w2 << 16; pre[5] = w2 & 0xFFFF0000u;             \
                    pre[6] = w3 << 16; pre[7] = w3 & 0xFFFF0000u;             \
                    unsigned cand[8];                                         \
                    _Pragma("unroll")                                         \
                    for (int k = 0; k < 8; ++k) cand[k] = pre[k] + bsh + vpk[k];\
                    unsigned c01 = cand[0] < cand[1] ? cand[0] : cand[1];     \
                    unsigned c23 = cand[2] < cand[3] ? cand[2] : cand[3];     \
                    unsigned c45 = cand[4] < cand[5] ? cand[4] : cand[5];     \
                    unsigned c67 = cand[6] < cand[7] ? cand[6] : cand[7];     \
                    unsigned ca = c01 < c23 ? c01 : c23;                      \
                    unsigned cb = c45 < c67 ? c45 : c67;                      \
                    unsigned tc = ca < cb ? ca : cb;                          \
                    unsigned mm = tc < treeOld ? tc : treeOld;                \
                    const unsigned g = __reduce_min_sync(FULL, mm);           \
                    t_i   = g & 0x1FF00u;                                     \
                    smask = g & 0x7FFE0000u;                                  \
                    const int j1 = (int)(g & 0xFFu);                          \
                    if (t_i == 0) {                                           \
                        jfinal = j1; mush = smask;                            \
                        _Pragma("unroll")                                     \
                        for (int k = 0; k < 8; ++k)                           \
                            if (cand[k] < Dp[k]) { Dp[k] = cand[k]; way[k] = j0; }\
                        goto search_done;                                     \
                    }                                                         \
                    u0sh = *(const unsigned*)((const char*)u_ + (t_i >> 6));  \
                    _Pragma("unroll")                                         \
                    for (int k = 0; k < 8; ++k)                               \
                        if (cand[k] < Dp[k]) { Dp[k] = cand[k]; way[k] = j0; }\
                    _Pragma("unroll")                                         \
                    for (int k = 0; k < 8; ++k)                               \
                        if (((lane << 3) + k) == j1) {                        \
                            vpk[k] += 0x80000000u;                            \
                            Dp[k]  |= 0x80000000u;                            \
                        }                                                     \
                    {                                                         \
                        unsigned m01 = Dp[0] < Dp[1] ? Dp[0] : Dp[1];         \
                        unsigned m23 = Dp[2] < Dp[3] ? Dp[2] : Dp[3];         \
                        unsigned m45 = Dp[4] < Dp[5] ? Dp[4] : Dp[5];         \
                        unsigned m67 = Dp[6] < Dp[7] ? Dp[6] : Dp[7];         \
                        unsigned maa = m01 < m23 ? m01 : m23;                 \
                        unsigned mbb = m45 < m67 ? m45 : m67;                 \
                        treeOld = maa < mbb ? maa : mbb;                      \
                    }                                                         \
                    j0 = j1;                                                  \
                }

                while (true) {
                    DIJK_STEP
                    DIJK_STEP
                }
search_done: ;
#undef DIJK_STEP

                // publish way pointers
                {
                    unsigned a0 = ((unsigned)way[0] & 0xFFFFu) | ((unsigned)way[1] << 16);
                    unsigned a1 = ((unsigned)way[2] & 0xFFFFu) | ((unsigned)way[3] << 16);
                    unsigned a2 = ((unsigned)way[4] & 0xFFFFu) | ((unsigned)way[5] << 16);
                    unsigned a3 = ((unsigned)way[6] & 0xFFFFu) | ((unsigned)way[7] << 16);
                    ((uint4*)way0_)[lane] = make_uint4(a0, a1, a2, a3);
                }
                __syncwarp();
                if (lane == 0) {
                    int cur = jfinal;                      // augment along path
                    while (true) {
                        int pr = way0_[cur];
                        if (pr == JROOT) { p_[cur + 1] = (unsigned short)i; break; }
                        p_[cur + 1] = p_[pr + 1];
                        cur = pr;
                    }
                    u_[i] += mush;
                }
                // deferred dual updates from frozen Dp words (shifted domain).
                // frozen <=> bit31 set and != 0xFFFFFFFF.
#pragma unroll
                for (int k = 0; k < 8; ++k) {
                    unsigned dk = Dp[k];
                    if ((dk >> 31) && dk != 0xFFFFFFFFu) {
                        unsigned adjsh = mush - (dk & 0x7FFE0000u);  // (mu-Sfz)<<17
                        vsh[k] -= adjsh;
                        u_[(dk >> 8) & 0x1FFu] += adjsh;   // distinct rows: race-free
                    }
                }
                __syncwarp();
            }
        }
    }
    __syncthreads();

    // ---- Phase 3: gather matched fp32 distances, deterministic block sum ----
    {
        const int j   = tid + 1;
        const int row = p_[j];
        float val = g_dist[((size_t)b << 16) + (size_t)(row - 1) * N + (j - 1)];
        double d = (double)val;
#pragma unroll
        for (int off = 16; off > 0; off >>= 1)
            d += __shfl_down_sync(0xffffffffu, d, off);
        if ((tid & 31) == 0) sred[tid >> 5] = d;
        __syncthreads();
        if (tid == 0) {
            double t = 0.0;
#pragma unroll
            for (int w = 0; w < 8; ++w) t += sred[w];   // fixed order
            g_bsum[b] = t;
        }
    }
}

// ---------------------------------------------------------------------------
// Kernel C: deterministic final reduce + mean
// ---------------------------------------------------------------------------
__global__ void finalize_kernel(float* __restrict__ out) {
    double t = 0.0;
#pragma unroll
    for (int b = 0; b < BATCH; ++b) t += g_bsum[b];
    out[0] = (float)(t / (double)(BATCH * N));
}

// ---------------------------------------------------------------------------
extern "C" void kernel_launch(void* const* d_in, const int* in_sizes, int n_in,
                              void* d_out, int out_size) {
    const float* pred = (const float*)d_in[0];
    const float* tgt  = (const float*)d_in[1];
    float* out = (float*)d_out;

    cudaFuncSetAttribute(hungarian_kernel,
                         cudaFuncAttributeMaxDynamicSharedMemorySize, SMEM_B);

    dist_kernel<<<dim3(16, 16, 16), 256>>>(pred, tgt);
    hungarian_kernel<<<BATCH, 256, SMEM_B>>>();
    finalize_kernel<<<1, 1>>>(out);
}

// round 13
// speedup vs baseline: 1.0628x; 1.0628x over previous
#include <cuda_runtime.h>
#include <cuda_bf16.h>

#define BATCH 16
#define N 256
#define DIM 128

// Scratch (device globals: allocation-free per harness rules)
__device__ float          g_dist[BATCH * N * N];   // 4 MB fp32 distances
__device__ unsigned short g_cost[BATCH * N * N];   // 2 MB u16: (quantized q)<<2
__device__ double         g_bsum[BATCH];           // per-batch matched sums

#define QSCALE 128.0f
#define QMAX   4095    // q <= 4095 -> d = S+rc <= 8190 < 2^13; cand < 2^31 (tag-safe)

// ---------------------------------------------------------------------------
// Kernel A: pairwise L2 distances + quantization (stored pre-shifted <<2).
// ---------------------------------------------------------------------------
__global__ __launch_bounds__(256) void dist_kernel(const float* __restrict__ pred,
                                                   const float* __restrict__ tgt) {
    __shared__ float sp[16 * 132];
    __shared__ float st[16 * 132];
    const int b  = blockIdx.z;
    const int rt = blockIdx.y;
    const int ct = blockIdx.x;
    const int tid = threadIdx.x;

    const float4* p4 = (const float4*)(pred + (size_t)(b * N + rt * 16) * DIM);
    const float4* t4 = (const float4*)(tgt  + (size_t)(b * N + ct * 16) * DIM);
    for (int idx = tid; idx < 512; idx += 256) {
        int r = idx >> 5, c = idx & 31;
        *(float4*)&sp[r * 132 + c * 4] = p4[idx];
        *(float4*)&st[r * 132 + c * 4] = t4[idx];
    }
    __syncthreads();

    const int ti = tid >> 4;
    const int tj = tid & 15;
    float acc = 0.f;
#pragma unroll
    for (int d4 = 0; d4 < 32; ++d4) {
        float4 a = *(const float4*)&sp[ti * 132 + d4 * 4];
        float4 c = *(const float4*)&st[tj * 132 + d4 * 4];
        float dx = a.x - c.x, dy = a.y - c.y, dz = a.z - c.z, dw = a.w - c.w;
        acc += dx * dx + dy * dy + dz * dz + dw * dw;
    }
    float dd = sqrtf(acc);
    size_t o = ((size_t)b << 16) + (size_t)(rt * 16 + ti) * N + (ct * 16 + tj);
    g_dist[o] = dd;
    int q = __float2int_rn(dd * QSCALE);
    q = q > QMAX ? QMAX : q;
    g_cost[o] = (unsigned short)(q << 2);   // pre-shifted: w<<16 / w&0xFFFF0000 => q<<18
}

// ---------------------------------------------------------------------------
// Kernel B: per-batch Jonker-Volgenant LSA on pre-shifted u16 costs in shared.
//   Warp-0 Dijkstra, (d<<18 | p<<9 | j) packed redux-min, inline relax (R11
//   structure). p<<9 in the pack IS the row byte offset (512 B row stride):
//   next-row address = cbase + (g & 0x3FE00) — one level shorter chain.
//   All dual quantities (u, v, S) live pre-shifted by 18.
//   Freeze: vpk += 2^31 (future cands wrap-free >= 2^31, never win, never
//   beat frozen Dp) and Dp |= 2^31 (tree exclusion). Duals decoded from
//   frozen Dp at search end in the shifted domain.
// ---------------------------------------------------------------------------
// dynamic smem layout (bytes)
#define OFF_COST 0                       // u16[65536] = 131072
#define OFF_U    131072                  // u32[257]   = 1028  -> 132100
#define OFF_P    132100                  // u16[257]   = 514   -> 132614
#define OFF_WAY  132624                  // u16[256]   = 512   -> 133136 (16-aligned)
#define OFF_RMIN 133136                  // u16[256]   = 512   -> 133648 (16-aligned)
#define OFF_ROWT 133648                  // u32[8]     = 32    -> 133680
#define OFF_SRED 133680                  // double[8]  = 64    -> 133744
#define SMEM_B   133744

#define JROOT 0x1FF                      // way-chain root marker

extern __shared__ char s_raw[];

__global__ __launch_bounds__(256) void hungarian_kernel() {
    const int b   = blockIdx.x;
    const int tid = threadIdx.x;

    unsigned short* cost  = (unsigned short*)(s_raw + OFF_COST);
    unsigned*       u_    = (unsigned*)(s_raw + OFF_U);         // u<<18, 1-based
    unsigned short* p_    = (unsigned short*)(s_raw + OFF_P);   // p_[j+1], 0 = free
    unsigned short* way0_ = (unsigned short*)(s_raw + OFF_WAY); // 0-based cols
    unsigned short* srmin = (unsigned short*)(s_raw + OFF_RMIN);
    unsigned*       srowt = (unsigned*)(s_raw + OFF_ROWT);
    double*         sred  = (double*)(s_raw + OFF_SRED);

    // ---- Phase 1: copy quantized costs into shared, init state ----
    const uint4* csrc = (const uint4*)(g_cost + ((size_t)b << 16));
    uint4* cdst = (uint4*)cost;
    for (int idx = tid; idx < (N * N) / 8; idx += 256) cdst[idx] = csrc[idx];
    for (int i = tid; i < N + 1; i += 256) { u_[i] = 0u; p_[i] = 0; }
    __syncthreads();

    // ---- Phase 2: warp 0 runs the LSA ----
    if (tid < 32) {
        const unsigned FULL = 0xffffffffu;
        const int lane = tid;

        // Column reduction in the stored (q<<2) domain.
        unsigned vmin[8]; int rmin[8];
#pragma unroll
        for (int k = 0; k < 8; ++k) { vmin[k] = 0xFFFFFFFFu; rmin[k] = 0; }
        for (int r = 0; r < N; ++r) {
            uint4 cc = ((const uint4*)(cost + (r << 8)))[lane];
            unsigned wv[4] = {cc.x, cc.y, cc.z, cc.w};
#pragma unroll
            for (int k = 0; k < 8; ++k) {
                unsigned c = (wv[k >> 1] >> ((k & 1) * 16)) & 0xFFFFu;
                if (c < vmin[k]) { vmin[k] = c; rmin[k] = r; }
            }
        }
        {
            unsigned a0 = (unsigned)rmin[0] | ((unsigned)rmin[1] << 16);
            unsigned a1 = (unsigned)rmin[2] | ((unsigned)rmin[3] << 16);
            unsigned a2 = (unsigned)rmin[4] | ((unsigned)rmin[5] << 16);
            unsigned a3 = (unsigned)rmin[6] | ((unsigned)rmin[7] << 16);
            ((uint4*)srmin)[lane] = make_uint4(a0, a1, a2, a3);
        }
        if (lane < 8) srowt[lane] = 0u;
        __syncwarp();
        // Greedy pre-assignment: column j -> rmin[j] if that row is still free.
        if (lane == 0) {
            for (int j = 0; j < N; ++j) {
                int r = srmin[j];
                unsigned wd = srowt[r >> 5];
                if (!((wd >> (r & 31)) & 1u)) {
                    srowt[r >> 5] = wd | (1u << (r & 31));
                    p_[j + 1] = (unsigned short)(r + 1);
                }
            }
        }
        __syncwarp();

        unsigned vsh[8];                   // v<<18 == (stored q<<2)<<16
#pragma unroll
        for (int k = 0; k < 8; ++k) vsh[k] = vmin[k] << 16;
        unsigned rt[8];
#pragma unroll
        for (int w = 0; w < 8; ++w) rt[w] = srowt[w];

        // base pointer for this lane's 16-byte row slice; row i0 (1-based) is
        // at byte offset i0*512 - 512, and t2 = p<<9 = i0*512 straight from g.
        const char* cbase = (const char*)cost - 512 + lane * 16;

        // ---- Dijkstra for each unassigned row ----
        for (int w = 0; w < 8; ++w) {
            unsigned freeb = ~rt[w];
            while (freeb) {
                const int bz = __ffs(freeb) - 1;
                freeb &= freeb - 1;
                const int i = w * 32 + bz + 1;     // 1-based start row; u_[i]==0

                unsigned vpk[8], Dp[8];
                int way[8];
#pragma unroll
                for (int k = 0; k < 8; ++k) {
                    int j = (lane << 3) + k;
                    vpk[k] = (((unsigned)p_[j + 1] << 9) | (unsigned)j) - vsh[k];
                    Dp[k] = 0xFFFFFFFFu;
                    way[k] = JROOT;
                }

                unsigned t2 = (unsigned)i << 9;    // = i0 * 512 (row byte offset)
                unsigned smask = 0u, u0sh = 0u, mush;
                int j0 = JROOT, jfinal;

                while (true) {
                    const uint4 cc = *(const uint4*)(cbase + t2);
                    const unsigned bsh = smask - u0sh;       // (S-u)<<18 mod 2^32
                    const unsigned w0 = cc.x, w1 = cc.y, w2 = cc.z, w3 = cc.w;
                    unsigned pre[8];
                    pre[0] = w0 << 16; pre[1] = w0 & 0xFFFF0000u;
                    pre[2] = w1 << 16; pre[3] = w1 & 0xFFFF0000u;
                    pre[4] = w2 << 16; pre[5] = w2 & 0xFFFF0000u;
                    pre[6] = w3 << 16; pre[7] = w3 & 0xFFFF0000u;
                    unsigned cand[8];
#pragma unroll
                    for (int k = 0; k < 8; ++k) cand[k] = pre[k] + bsh + vpk[k];
                    bool ge[8];
#pragma unroll
                    for (int k = 0; k < 8; ++k) ge[k] = cand[k] < Dp[k];
#pragma unroll
                    for (int k = 0; k < 8; ++k) Dp[k] = umin(Dp[k], cand[k]);
#pragma unroll
                    for (int k = 0; k < 8; ++k) way[k] = ge[k] ? j0 : way[k];

                    unsigned m01 = Dp[0] < Dp[1] ? Dp[0] : Dp[1];
                    unsigned m23 = Dp[2] < Dp[3] ? Dp[2] : Dp[3];
                    unsigned m45 = Dp[4] < Dp[5] ? Dp[4] : Dp[5];
                    unsigned m67 = Dp[6] < Dp[7] ? Dp[6] : Dp[7];
                    unsigned ma = m01 < m23 ? m01 : m23;
                    unsigned mb = m45 < m67 ? m45 : m67;
                    const unsigned g = __reduce_min_sync(FULL, ma < mb ? ma : mb);

                    t2    = g & 0x0003FE00u;               // p<<9 = row byte offset
                    smask = g & 0x7FFC0000u;               // S<<18
                    const int j1 = (int)(g & 0xFFu);
                    if (t2 == 0) { jfinal = j1; mush = smask; break; }
                    u0sh = *(const unsigned*)((const char*)u_ + (t2 >> 7)); // p*4
                    // freeze j1: future cands land in [2^31,2^32) wrap-free,
                    // never win, never beat frozen Dp; Dp bit31 excludes it
                    // from the tree.
#pragma unroll
                    for (int k = 0; k < 8; ++k)
                        if (((lane << 3) + k) == j1) {
                            vpk[k] += 0x80000000u;
                            Dp[k]  |= 0x80000000u;
                        }
                    j0 = j1;
                }

                // publish way pointers
                {
                    unsigned a0 = ((unsigned)way[0] & 0xFFFFu) | ((unsigned)way[1] << 16);
                    unsigned a1 = ((unsigned)way[2] & 0xFFFFu) | ((unsigned)way[3] << 16);
                    unsigned a2 = ((unsigned)way[4] & 0xFFFFu) | ((unsigned)way[5] << 16);
                    unsigned a3 = ((unsigned)way[6] & 0xFFFFu) | ((unsigned)way[7] << 16);
                    ((uint4*)way0_)[lane] = make_uint4(a0, a1, a2, a3);
                }
                __syncwarp();
                if (lane == 0) {
                    int cur = jfinal;                      // augment along path
                    while (true) {
                        int pr = way0_[cur];
                        if (pr == JROOT) { p_[cur + 1] = (unsigned short)i; break; }
                        p_[cur + 1] = p_[pr + 1];
                        cur = pr;
                    }
                    u_[i] += mush;
                }
                // deferred dual updates from frozen Dp words (shifted domain).
                // frozen <=> bit31 set and != 0xFFFFFFFF.
#pragma unroll
                for (int k = 0; k < 8; ++k) {
                    unsigned dk = Dp[k];
                    if ((dk >> 31) && dk != 0xFFFFFFFFu) {
                        unsigned adjsh = mush - (dk & 0x7FFC0000u);  // (mu-Sfz)<<18
                        vsh[k] -= adjsh;
                        u_[(dk >> 9) & 0x1FFu] += adjsh;   // distinct rows: race-free
                    }
                }
                __syncwarp();
            }
        }
    }
    __syncthreads();

    // ---- Phase 3: gather matched fp32 distances, deterministic block sum ----
    {
        const int j   = tid + 1;
        const int row = p_[j];
        float val = g_dist[((size_t)b << 16) + (size_t)(row - 1) * N + (j - 1)];
        double d = (double)val;
#pragma unroll
        for (int off = 16; off > 0; off >>= 1)
            d += __shfl_down_sync(0xffffffffu, d, off);
        if ((tid & 31) == 0) sred[tid >> 5] = d;
        __syncthreads();
        if (tid == 0) {
            double t = 0.0;
#pragma unroll
            for (int w = 0; w < 8; ++w) t += sred[w];   // fixed order
            g_bsum[b] = t;
        }
    }
}

// ---------------------------------------------------------------------------
// Kernel C: deterministic final reduce + mean
// ---------------------------------------------------------------------------
__global__ void finalize_kernel(float* __restrict__ out) {
    double t = 0.0;
#pragma unroll
    for (int b = 0; b < BATCH; ++b) t += g_bsum[b];
    out[0] = (float)(t / (double)(BATCH * N));
}

// ---------------------------------------------------------------------------
extern "C" void kernel_launch(void* const* d_in, const int* in_sizes, int n_in,
                              void* d_out, int out_size) {
    const float* pred = (const float*)d_in[0];
    const float* tgt  = (const float*)d_in[1];
    float* out = (float*)d_out;

    cudaFuncSetAttribute(hungarian_kernel,
                         cudaFuncAttributeMaxDynamicSharedMemorySize, SMEM_B);

    dist_kernel<<<dim3(16, 16, 16), 256>>>(pred, tgt);
    hungarian_kernel<<<BATCH, 256, SMEM_B>>>();
    finalize_kernel<<<1, 1>>>(out);
}

// round 14
// speedup vs baseline: 1.0853x; 1.0212x over previous
#include <cuda_runtime.h>
#include <cuda_bf16.h>

#define BATCH 16
#define N 256
#define DIM 128

// Scratch (device globals: allocation-free per harness rules)
__device__ float          g_dist[BATCH * N * N];   // 4 MB fp32 distances
__device__ unsigned short g_cost[BATCH * N * N];   // 2 MB u16: (quantized q)<<2
__device__ double         g_bsum[BATCH];           // per-batch matched sums

#define QSCALE 128.0f
#define QMAX   4095    // q <= 4095 -> d = S+rc <= 8190 < 2^13; cand < 2^31 (tag-safe)

// ---------------------------------------------------------------------------
// Kernel A: pairwise L2 distances + quantization (stored pre-shifted <<2).
// ---------------------------------------------------------------------------
__global__ __launch_bounds__(256) void dist_kernel(const float* __restrict__ pred,
                                                   const float* __restrict__ tgt) {
    __shared__ float sp[16 * 132];
    __shared__ float st[16 * 132];
    const int b  = blockIdx.z;
    const int rt = blockIdx.y;
    const int ct = blockIdx.x;
    const int tid = threadIdx.x;

    const float4* p4 = (const float4*)(pred + (size_t)(b * N + rt * 16) * DIM);
    const float4* t4 = (const float4*)(tgt  + (size_t)(b * N + ct * 16) * DIM);
    for (int idx = tid; idx < 512; idx += 256) {
        int r = idx >> 5, c = idx & 31;
        *(float4*)&sp[r * 132 + c * 4] = p4[idx];
        *(float4*)&st[r * 132 + c * 4] = t4[idx];
    }
    __syncthreads();

    const int ti = tid >> 4;
    const int tj = tid & 15;
    float acc = 0.f;
#pragma unroll
    for (int d4 = 0; d4 < 32; ++d4) {
        float4 a = *(const float4*)&sp[ti * 132 + d4 * 4];
        float4 c = *(const float4*)&st[tj * 132 + d4 * 4];
        float dx = a.x - c.x, dy = a.y - c.y, dz = a.z - c.z, dw = a.w - c.w;
        acc += dx * dx + dy * dy + dz * dz + dw * dw;
    }
    float dd = sqrtf(acc);
    size_t o = ((size_t)b << 16) + (size_t)(rt * 16 + ti) * N + (ct * 16 + tj);
    g_dist[o] = dd;
    int q = __float2int_rn(dd * QSCALE);
    q = q > QMAX ? QMAX : q;
    g_cost[o] = (unsigned short)(q << 2);   // pre-shifted: w<<16 / w&0xFFFF0000 => q<<18
}

// ---------------------------------------------------------------------------
// Kernel B: per-batch Jonker-Volgenant LSA on pre-shifted u16 costs in shared.
//   Warp-0 Dijkstra, (d<<18 | p<<9 | j) packed redux-min, inline relax.
//   p<<9 in the pack IS the row byte offset (512 B row stride). Duals live
//   pre-shifted by 18. Freeze: vpk += 2^31 (wrap-free cands never win / never
//   beat frozen Dp), Dp |= 2^31 (tree exclusion). Duals decoded from frozen
//   Dp at search end. Dp tree uses DPX __vimin3_u32 (2 levels instead of 3);
//   step body 2x-unrolled (relax precedes redux, so break is clean anywhere).
// ---------------------------------------------------------------------------
// dynamic smem layout (bytes)
#define OFF_COST 0                       // u16[65536] = 131072
#define OFF_U    131072                  // u32[257]   = 1028  -> 132100
#define OFF_P    132100                  // u16[257]   = 514   -> 132614
#define OFF_WAY  132624                  // u16[256]   = 512   -> 133136 (16-aligned)
#define OFF_RMIN 133136                  // u16[256]   = 512   -> 133648 (16-aligned)
#define OFF_ROWT 133648                  // u32[8]     = 32    -> 133680
#define OFF_SRED 133680                  // double[8]  = 64    -> 133744
#define SMEM_B   133744

#define JROOT 0x1FF                      // way-chain root marker

extern __shared__ char s_raw[];

__global__ __launch_bounds__(256) void hungarian_kernel() {
    const int b   = blockIdx.x;
    const int tid = threadIdx.x;

    unsigned short* cost  = (unsigned short*)(s_raw + OFF_COST);
    unsigned*       u_    = (unsigned*)(s_raw + OFF_U);         // u<<18, 1-based
    unsigned short* p_    = (unsigned short*)(s_raw + OFF_P);   // p_[j+1], 0 = free
    unsigned short* way0_ = (unsigned short*)(s_raw + OFF_WAY); // 0-based cols
    unsigned short* srmin = (unsigned short*)(s_raw + OFF_RMIN);
    unsigned*       srowt = (unsigned*)(s_raw + OFF_ROWT);
    double*         sred  = (double*)(s_raw + OFF_SRED);

    // ---- Phase 1: copy quantized costs into shared, init state ----
    const uint4* csrc = (const uint4*)(g_cost + ((size_t)b << 16));
    uint4* cdst = (uint4*)cost;
    for (int idx = tid; idx < (N * N) / 8; idx += 256) cdst[idx] = csrc[idx];
    for (int i = tid; i < N + 1; i += 256) { u_[i] = 0u; p_[i] = 0; }
    __syncthreads();

    // ---- Phase 2: warp 0 runs the LSA ----
    if (tid < 32) {
        const unsigned FULL = 0xffffffffu;
        const int lane = tid;

        // Column reduction in the stored (q<<2) domain.
        unsigned vmin[8]; int rmin[8];
#pragma unroll
        for (int k = 0; k < 8; ++k) { vmin[k] = 0xFFFFFFFFu; rmin[k] = 0; }
        for (int r = 0; r < N; ++r) {
            uint4 cc = ((const uint4*)(cost + (r << 8)))[lane];
            unsigned wv[4] = {cc.x, cc.y, cc.z, cc.w};
#pragma unroll
            for (int k = 0; k < 8; ++k) {
                unsigned c = (wv[k >> 1] >> ((k & 1) * 16)) & 0xFFFFu;
                if (c < vmin[k]) { vmin[k] = c; rmin[k] = r; }
            }
        }
        {
            unsigned a0 = (unsigned)rmin[0] | ((unsigned)rmin[1] << 16);
            unsigned a1 = (unsigned)rmin[2] | ((unsigned)rmin[3] << 16);
            unsigned a2 = (unsigned)rmin[4] | ((unsigned)rmin[5] << 16);
            unsigned a3 = (unsigned)rmin[6] | ((unsigned)rmin[7] << 16);
            ((uint4*)srmin)[lane] = make_uint4(a0, a1, a2, a3);
        }
        if (lane < 8) srowt[lane] = 0u;
        __syncwarp();
        // Greedy pre-assignment: column j -> rmin[j] if that row is still free.
        if (lane == 0) {
            for (int j = 0; j < N; ++j) {
                int r = srmin[j];
                unsigned wd = srowt[r >> 5];
                if (!((wd >> (r & 31)) & 1u)) {
                    srowt[r >> 5] = wd | (1u << (r & 31));
                    p_[j + 1] = (unsigned short)(r + 1);
                }
            }
        }
        __syncwarp();

        unsigned vsh[8];                   // v<<18 == (stored q<<2)<<16
#pragma unroll
        for (int k = 0; k < 8; ++k) vsh[k] = vmin[k] << 16;
        unsigned rt[8];
#pragma unroll
        for (int w = 0; w < 8; ++w) rt[w] = srowt[w];

        // base pointer for this lane's 16-byte row slice; row i0 (1-based) is
        // at byte offset i0*512 - 512, and t2 = p<<9 = i0*512 straight from g.
        const char* cbase = (const char*)cost - 512 + lane * 16;

        // ---- Dijkstra for each unassigned row ----
        for (int w = 0; w < 8; ++w) {
            unsigned freeb = ~rt[w];
            while (freeb) {
                const int bz = __ffs(freeb) - 1;
                freeb &= freeb - 1;
                const int i = w * 32 + bz + 1;     // 1-based start row; u_[i]==0

                unsigned vpk[8], Dp[8];
                int way[8];
#pragma unroll
                for (int k = 0; k < 8; ++k) {
                    int j = (lane << 3) + k;
                    vpk[k] = (((unsigned)p_[j + 1] << 9) | (unsigned)j) - vsh[k];
                    Dp[k] = 0xFFFFFFFFu;
                    way[k] = JROOT;
                }

                unsigned t2 = (unsigned)i << 9;    // = i0 * 512 (row byte offset)
                unsigned smask = 0u, u0sh = 0u, mush;
                int j0 = JROOT, jfinal;

// One Dijkstra step (inline relax BEFORE redux => break path needs no fixup).
#define DIJK_STEP                                                             \
                {                                                             \
                    const uint4 cc = *(const uint4*)(cbase + t2);             \
                    const unsigned bsh = smask - u0sh;                        \
                    const unsigned w0 = cc.x, w1 = cc.y, w2 = cc.z, w3 = cc.w;\
                    unsigned pre[8];                                          \
                    pre[0] = w0 << 16; pre[1] = w0 & 0xFFFF0000u;             \
                    pre[2] = w1 << 16; pre[3] = w1 & 0xFFFF0000u;             \
                    pre[4] = w2 << 16; pre[5] = w2 & 0xFFFF0000u;             \
                    pre[6] = w3 << 16; pre[7] = w3 & 0xFFFF0000u;             \
                    unsigned cand[8];                                         \
                    _Pragma("unroll")                                         \
                    for (int k = 0; k < 8; ++k) cand[k] = pre[k] + bsh + vpk[k];\
                    bool ge[8];                                               \
                    _Pragma("unroll")                                         \
                    for (int k = 0; k < 8; ++k) ge[k] = cand[k] < Dp[k];      \
                    _Pragma("unroll")                                         \
                    for (int k = 0; k < 8; ++k) Dp[k] = umin(Dp[k], cand[k]); \
                    _Pragma("unroll")                                         \
                    for (int k = 0; k < 8; ++k) way[k] = ge[k] ? j0 : way[k]; \
                    unsigned ta = __vimin3_u32(Dp[0], Dp[1], Dp[2]);          \
                    unsigned tb = __vimin3_u32(Dp[3], Dp[4], Dp[5]);          \
                    unsigned tcm = umin(Dp[6], Dp[7]);                        \
                    unsigned mm = __vimin3_u32(ta, tb, tcm);                  \
                    const unsigned g = __reduce_min_sync(FULL, mm);           \
                    t2    = g & 0x0003FE00u;               /* p<<9 */         \
                    smask = g & 0x7FFC0000u;               /* S<<18 */        \
                    const int j1 = (int)(g & 0xFFu);                          \
                    if (t2 == 0) { jfinal = j1; mush = smask; goto search_done; }\
                    u0sh = *(const unsigned*)((const char*)u_ + (t2 >> 7));   \
                    _Pragma("unroll")                                         \
                    for (int k = 0; k < 8; ++k)                               \
                        if (((lane << 3) + k) == j1) {                        \
                            vpk[k] += 0x80000000u;                            \
                            Dp[k]  |= 0x80000000u;                            \
                        }                                                     \
                    j0 = j1;                                                  \
                }

                while (true) {
                    DIJK_STEP
                    DIJK_STEP
                }
search_done: ;
#undef DIJK_STEP

                // publish way pointers
                {
                    unsigned a0 = ((unsigned)way[0] & 0xFFFFu) | ((unsigned)way[1] << 16);
                    unsigned a1 = ((unsigned)way[2] & 0xFFFFu) | ((unsigned)way[3] << 16);
                    unsigned a2 = ((unsigned)way[4] & 0xFFFFu) | ((unsigned)way[5] << 16);
                    unsigned a3 = ((unsigned)way[6] & 0xFFFFu) | ((unsigned)way[7] << 16);
                    ((uint4*)way0_)[lane] = make_uint4(a0, a1, a2, a3);
                }
                __syncwarp();
                if (lane == 0) {
                    int cur = jfinal;                      // augment along path
                    while (true) {
                        int pr = way0_[cur];
                        if (pr == JROOT) { p_[cur + 1] = (unsigned short)i; break; }
                        p_[cur + 1] = p_[pr + 1];
                        cur = pr;
                    }
                    u_[i] += mush;
                }
                // deferred dual updates from frozen Dp words (shifted domain).
                // frozen <=> bit31 set and != 0xFFFFFFFF.
#pragma unroll
                for (int k = 0; k < 8; ++k) {
                    unsigned dk = Dp[k];
                    if ((dk >> 31) && dk != 0xFFFFFFFFu) {
                        unsigned adjsh = mush - (dk & 0x7FFC0000u);  // (mu-Sfz)<<18
                        vsh[k] -= adjsh;
                        u_[(dk >> 9) & 0x1FFu] += adjsh;   // distinct rows: race-free
                    }
                }
                __syncwarp();
            }
        }
    }
    __syncthreads();

    // ---- Phase 3: gather matched fp32 distances, deterministic block sum ----
    {
        const int j   = tid + 1;
        const int row = p_[j];
        float val = g_dist[((size_t)b << 16) + (size_t)(row - 1) * N + (j - 1)];
        double d = (double)val;
#pragma unroll
        for (int off = 16; off > 0; off >>= 1)
            d += __shfl_down_sync(0xffffffffu, d, off);
        if ((tid & 31) == 0) sred[tid >> 5] = d;
        __syncthreads();
        if (tid == 0) {
            double t = 0.0;
#pragma unroll
            for (int w = 0; w < 8; ++w) t += sred[w];   // fixed order
            g_bsum[b] = t;
        }
    }
}

// ---------------------------------------------------------------------------
// Kernel C: deterministic final reduce + mean
// ---------------------------------------------------------------------------
__global__ void finalize_kernel(float* __restrict__ out) {
    double t = 0.0;
#pragma unroll
    for (int b = 0; b < BATCH; ++b) t += g_bsum[b];
    out[0] = (float)(t / (double)(BATCH * N));
}

// ---------------------------------------------------------------------------
extern "C" void kernel_launch(void* const* d_in, const int* in_sizes, int n_in,
                              void* d_out, int out_size) {
    const float* pred = (const float*)d_in[0];
    const float* tgt  = (const float*)d_in[1];
    float* out = (float*)d_out;

    cudaFuncSetAttribute(hungarian_kernel,
                         cudaFuncAttributeMaxDynamicSharedMemorySize, SMEM_B);

    dist_kernel<<<dim3(16, 16, 16), 256>>>(pred, tgt);
    hungarian_kernel<<<BATCH, 256, SMEM_B>>>();
    finalize_kernel<<<1, 1>>>(out);
}